// round 1
// baseline (speedup 1.0000x reference)
#include <cuda_runtime.h>
#include <cstddef>

#define HH 1024
#define II 256
#define OO 256
#define BB 64
#define TT 512
#define NCTA 128
#define RPC 10   // rows of the combined [HH+OO] matrix per CTA (128*10 = 1280)

// -------- static device scratch (allowed; no runtime allocation) ----------
__device__ float g_xproj[(size_t)TT * HH * BB];   // [t][h][b]  x_t @ W_in^T + b_in
__device__ float g_hall [(size_t)TT * HH * BB];   // slot t holds h_{t+1}, layout [h][b]
__device__ float g_outs [(size_t)TT * OO * BB];   // [t][o][b]
__device__ unsigned g_cnt = 0;
__device__ volatile unsigned g_gen = 0;

// -------- packed f32x2 helpers (Blackwell FFMA2 path) ---------------------
__device__ __forceinline__ unsigned long long pack2(float w) {
    unsigned long long r; unsigned u = __float_as_uint(w);
    asm("mov.b64 %0, {%1, %1};" : "=l"(r) : "r"(u));
    return r;
}
__device__ __forceinline__ void fma2(unsigned long long& d, unsigned long long a, unsigned long long b) {
    asm("fma.rn.f32x2 %0, %1, %2, %3;" : "=l"(d) : "l"(a), "l"(b), "l"(d));
}
__device__ __forceinline__ unsigned long long add2(unsigned long long a, unsigned long long b) {
    unsigned long long r;
    asm("add.rn.f32x2 %0, %1, %2;" : "=l"(r) : "l"(a), "l"(b));
    return r;
}

// ==========================================================================
// Kernel 1: x_proj[t][h][b] = sum_i inputs[b][t][i] * w_in[h][i] + b_in[h]
// grid (H/64, T), 256 threads, 4x4 register tile per thread
// ==========================================================================
__global__ void __launch_bounds__(256) xproj_kernel(
    const float* __restrict__ inp, const float* __restrict__ w_in,
    const float* __restrict__ b_in)
{
    __shared__ float As[64][33];   // [h][i]
    __shared__ float Bs[32][68];   // [i][b], row stride 272B (16B aligned)
    const int t = blockIdx.y;
    const int hbase = blockIdx.x << 6;
    const int tid = threadIdx.x;
    const int tx = tid & 15, ty = tid >> 4;

    float acc[4][4];
#pragma unroll
    for (int a = 0; a < 4; ++a)
#pragma unroll
        for (int b = 0; b < 4; ++b) acc[a][b] = 0.f;

    for (int ic = 0; ic < II; ic += 32) {
#pragma unroll
        for (int n = tid; n < 64 * 32; n += 256) {
            int h = n >> 5, i = n & 31;
            As[h][i] = w_in[(size_t)(hbase + h) * II + ic + i];
        }
#pragma unroll
        for (int n = tid; n < 64 * 32; n += 256) {
            int b = n >> 5, i = n & 31;
            Bs[i][b] = inp[(size_t)b * (TT * II) + (size_t)t * II + ic + i];
        }
        __syncthreads();
#pragma unroll
        for (int i = 0; i < 32; ++i) {
            float a0 = As[ty * 4 + 0][i], a1 = As[ty * 4 + 1][i];
            float a2 = As[ty * 4 + 2][i], a3 = As[ty * 4 + 3][i];
            float4 bv = *reinterpret_cast<const float4*>(&Bs[i][tx << 2]);
            acc[0][0] += a0 * bv.x; acc[0][1] += a0 * bv.y; acc[0][2] += a0 * bv.z; acc[0][3] += a0 * bv.w;
            acc[1][0] += a1 * bv.x; acc[1][1] += a1 * bv.y; acc[1][2] += a1 * bv.z; acc[1][3] += a1 * bv.w;
            acc[2][0] += a2 * bv.x; acc[2][1] += a2 * bv.y; acc[2][2] += a2 * bv.z; acc[2][3] += a2 * bv.w;
            acc[3][0] += a3 * bv.x; acc[3][1] += a3 * bv.y; acc[3][2] += a3 * bv.z; acc[3][3] += a3 * bv.w;
        }
        __syncthreads();
    }
#pragma unroll
    for (int r = 0; r < 4; ++r) {
        int h = hbase + ty * 4 + r;
        float bi = b_in[h];
        float4 v = make_float4(acc[r][0] + bi, acc[r][1] + bi, acc[r][2] + bi, acc[r][3] + bi);
        *reinterpret_cast<float4*>(g_xproj + (size_t)t * (HH * BB) + (size_t)h * BB + (tx << 2)) = v;
    }
}

// ==========================================================================
// Kernel 2: persistent recurrent scan. 128 CTAs x 256 threads, all resident.
// CTA c owns rows [c*10, c*10+10) of the combined 1280x1024 weight matrix
// (rows < 1024 -> W_rec / h update ; rows >= 1024 -> W_out / output).
// Per iteration j (0..512): GEMM vs h_j (h_0 = 0 implicit), rec rows write
// h_{j+1} (slot j), out rows write out_{j-1}. One grid barrier per step.
// Threads: 16 k-slices x 16 b-groups, fp32x2 packed FMA, SMEM k-reduction.
// ==========================================================================
__global__ void __launch_bounds__(256, 1) rnn_step_kernel(
    const float* __restrict__ w_rec, const float* __restrict__ b_rec,
    const float* __restrict__ w_out, const float* __restrict__ b_out,
    const float* __restrict__ scale, const float* __restrict__ shift)
{
    extern __shared__ float smem[];
    float* Ws = smem;                                  // [HH*12] padded rows
    unsigned long long* red =
        reinterpret_cast<unsigned long long*>(smem + HH * 12);  // [16][RPC][32]

    const int tid = threadIdx.x;
    const int cta = blockIdx.x;
    const int row0 = cta * RPC;

    // stage this CTA's 10 weight rows once (reused for all 512 steps)
    for (int idx = tid; idx < RPC * HH; idx += 256) {
        int r = idx >> 10, k = idx & (HH - 1);
        int gr = row0 + r;
        float v = (gr < HH) ? w_rec[(size_t)gr * HH + k]
                            : w_out[(size_t)(gr - HH) * HH + k];
        Ws[k * 12 + r] = v;
    }
    __syncthreads();

    const int ks = tid >> 4;     // k-slice 0..15 (64 k each)
    const int bg = tid & 15;     // batch group 0..15 (4 b each)
    const int k0 = ks << 6;
    const int b0 = bg << 2;

    for (int j = 0; j <= TT; ++j) {
        unsigned long long acc[RPC][2];
#pragma unroll
        for (int r = 0; r < RPC; ++r) { acc[r][0] = 0ull; acc[r][1] = 0ull; }

        if (j > 0) {
            const float* hp = g_hall + (size_t)(j - 1) * (HH * BB) + (size_t)k0 * BB + b0;
            const float* wp = Ws + k0 * 12;
#pragma unroll 4
            for (int kk = 0; kk < 64; ++kk) {
                ulonglong2 hv = *reinterpret_cast<const ulonglong2*>(hp);
                hp += BB;
                float4 wa = *reinterpret_cast<const float4*>(wp);
                float4 wb = *reinterpret_cast<const float4*>(wp + 4);
                float2 wc = *reinterpret_cast<const float2*>(wp + 8);
                wp += 12;
                float wv[RPC] = {wa.x, wa.y, wa.z, wa.w, wb.x, wb.y, wb.z, wb.w, wc.x, wc.y};
#pragma unroll
                for (int r = 0; r < RPC; ++r) {
                    unsigned long long ww = pack2(wv[r]);
                    fma2(acc[r][0], ww, hv.x);
                    fma2(acc[r][1], ww, hv.y);
                }
            }
        }

        // k-slice reduction through SMEM
#pragma unroll
        for (int r = 0; r < RPC; ++r) {
            red[(ks * RPC + r) * 32 + (bg << 1)    ] = acc[r][0];
            red[(ks * RPC + r) * 32 + (bg << 1) + 1] = acc[r][1];
        }
        __syncthreads();

        for (int idx = tid; idx < RPC * 32; idx += 256) {
            int r = idx >> 5, bp = idx & 31;
            unsigned long long s = red[r * 32 + bp];
#pragma unroll
            for (int q = 1; q < 16; ++q) s = add2(s, red[(q * RPC + r) * 32 + bp]);
            unsigned ua, ub;
            asm("mov.b64 {%0, %1}, %2;" : "=r"(ua), "=r"(ub) : "l"(s));
            float y0 = __uint_as_float(ua), y1 = __uint_as_float(ub);
            int gr = row0 + r;
            int b = bp << 1;
            if (gr < HH) {
                if (j < TT) {   // h_{j+1} = relu(y + b_rec + x_j)
                    size_t base = (size_t)j * (HH * BB) + (size_t)gr * BB + b;
                    float2 x = *reinterpret_cast<const float2*>(g_xproj + base);
                    float br = b_rec[gr];
                    float h0v = fmaxf(y0 + br + x.x, 0.0f);
                    float h1v = fmaxf(y1 + br + x.y, 0.0f);
                    *reinterpret_cast<float2*>(g_hall + base) = make_float2(h0v, h1v);
                }
            } else {
                if (j > 0) {    // out_{j-1} = scale*(y + b_out) - shift
                    int o = gr - HH;
                    float sc = scale[o], bo = b_out[o], sh = shift[o];
                    size_t base = (size_t)(j - 1) * (OO * BB) + (size_t)o * BB + b;
                    *reinterpret_cast<float2*>(g_outs + base) =
                        make_float2(sc * (y0 + bo) - sh, sc * (y1 + bo) - sh);
                }
            }
        }

        // ---- grid barrier (generation counter; state self-resets) ----
        __syncthreads();
        if (tid == 0) {
            unsigned my = g_gen;
            __threadfence();
            if (atomicAdd(&g_cnt, 1u) == NCTA - 1) {
                g_cnt = 0;
                __threadfence();
                g_gen = my + 1;
            } else {
                while (g_gen == my) { }
                __threadfence();
            }
        }
        __syncthreads();
    }
}

// ==========================================================================
// Kernel 3: batched plane transpose  src[t][r][c] -> dst[c][t*R + r]
// ==========================================================================
__global__ void transpose_kernel(float* __restrict__ dst, int R, int which)
{
    __shared__ float tile[32][33];
    const float* src = which ? g_hall : g_outs;
    const int t = blockIdx.z;
    const int r0 = blockIdx.x << 5, c0 = blockIdx.y << 5;
    const int x = threadIdx.x, y = threadIdx.y;
    const float* s = src + (size_t)t * R * BB;
#pragma unroll
    for (int jj = 0; jj < 32; jj += 8)
        tile[y + jj][x] = s[(size_t)(r0 + y + jj) * BB + c0 + x];
    __syncthreads();
    const size_t TR = (size_t)TT * R;
#pragma unroll
    for (int jj = 0; jj < 32; jj += 8)
        dst[(size_t)(c0 + y + jj) * TR + (size_t)t * R + r0 + x] = tile[x][y + jj];
}

// ==========================================================================
extern "C" void kernel_launch(void* const* d_in, const int* in_sizes, int n_in,
                              void* d_out, int out_size)
{
    (void)in_sizes; (void)n_in; (void)out_size;
    const float* inputs = (const float*)d_in[0];
    const float* w_rec  = (const float*)d_in[1];
    const float* b_rec  = (const float*)d_in[2];
    const float* w_in   = (const float*)d_in[3];
    const float* b_in   = (const float*)d_in[4];
    const float* w_out  = (const float*)d_in[5];
    const float* b_out  = (const float*)d_in[6];
    const float* scale  = (const float*)d_in[7];
    const float* shift  = (const float*)d_in[8];
    float* out = (float*)d_out;

    xproj_kernel<<<dim3(HH / 64, TT), 256>>>(inputs, w_in, b_in);

    const int smem_bytes = HH * 12 * 4 + 16 * RPC * 32 * 8;   // 49152 + 40960 = 90112
    cudaFuncSetAttribute(rnn_step_kernel,
                         cudaFuncAttributeMaxDynamicSharedMemorySize, smem_bytes);
    rnn_step_kernel<<<NCTA, 256, smem_bytes>>>(w_rec, b_rec, w_out, b_out, scale, shift);

    // outs [b][t][o] then hids [b][t][h]
    transpose_kernel<<<dim3(OO / 32, BB / 32, TT), dim3(32, 8)>>>(out, OO, 0);
    transpose_kernel<<<dim3(HH / 32, BB / 32, TT), dim3(32, 8)>>>(
        out + (size_t)BB * TT * OO, HH, 1);
}

// round 2
// speedup vs baseline: 1.3023x; 1.3023x over previous
#include <cuda_runtime.h>
#include <cstddef>

#define HH 1024
#define II 256
#define OO 256
#define BB 64
#define TT 512
#define MAXR 20     // padded rows per CTA in SMEM (actual nrows <= 18)
#define NPAIR 9     // row-pair accumulators per thread

// -------- static device scratch ----------
__device__ float g_xproj[(size_t)TT * HH * BB];   // [t][h][b]
__device__ float g_hall [(size_t)TT * HH * BB];   // slot t holds h_{t+1}, [h][b]
__device__ float g_outs [(size_t)TT * OO * BB];   // [t][o][b]
__device__ unsigned g_cnt = 0;
__device__ volatile unsigned g_gen = 0;

// -------- packed f32x2 helpers ----------
__device__ __forceinline__ unsigned long long pack2(float w) {
    unsigned long long r; unsigned u = __float_as_uint(w);
    asm("mov.b64 %0, {%1, %1};" : "=l"(r) : "r"(u));
    return r;
}
__device__ __forceinline__ void fma2(unsigned long long& d, unsigned long long a, unsigned long long b) {
    asm("fma.rn.f32x2 %0, %1, %2, %3;" : "=l"(d) : "l"(a), "l"(b), "l"(d));
}
__device__ __forceinline__ unsigned long long add2(unsigned long long a, unsigned long long b) {
    unsigned long long r;
    asm("add.rn.f32x2 %0, %1, %2;" : "=l"(r) : "l"(a), "l"(b));
    return r;
}
__device__ __forceinline__ void unpack2(float& lo, float& hi, unsigned long long v) {
    unsigned a, b;
    asm("mov.b64 {%0, %1}, %2;" : "=r"(a), "=r"(b) : "l"(v));
    lo = __uint_as_float(a); hi = __uint_as_float(b);
}

// ==========================================================================
// Kernel 1: x_proj[t][h][b] = sum_i inputs[b][t][i] * w_in[h][i] + b_in[h]
// 64h x 64b tile per CTA, grid (H/64, T), 256 threads.
// Row-pair f32x2: acc[p] = {D[h0][b], D[h0+1][b]}.
// ==========================================================================
__global__ void __launch_bounds__(256) xproj_kernel(
    const float* __restrict__ inp, const float* __restrict__ w_in,
    const float* __restrict__ b_in)
{
    __shared__ float As[32][68];   // [i][h]
    __shared__ float Bs[32][68];   // [i][b]
    const int t = blockIdx.y;
    const int hbase = blockIdx.x << 6;
    const int tid = threadIdx.x;
    const int hg = tid >> 5;       // 8 h rows each
    const int bg = tid & 31;       // b pair 2*bg

    unsigned long long acc[4][2];
#pragma unroll
    for (int p = 0; p < 4; ++p) { acc[p][0] = 0ull; acc[p][1] = 0ull; }

    for (int ic = 0; ic < II; ic += 32) {
#pragma unroll
        for (int n = tid; n < 64 * 32; n += 256) {
            int h = n >> 5, i = n & 31;
            As[i][h] = w_in[(size_t)(hbase + h) * II + ic + i];
        }
#pragma unroll
        for (int n = tid; n < 64 * 32; n += 256) {
            int b = n >> 5, i = n & 31;
            Bs[i][b] = inp[(size_t)b * (TT * II) + (size_t)t * II + ic + i];
        }
        __syncthreads();
#pragma unroll
        for (int i = 0; i < 32; ++i) {
            ulonglong2 w01 = *reinterpret_cast<const ulonglong2*>(&As[i][hg << 3]);
            ulonglong2 w23 = *reinterpret_cast<const ulonglong2*>(&As[i][(hg << 3) + 4]);
            float2 xv = *reinterpret_cast<const float2*>(&Bs[i][bg << 1]);
            unsigned long long x0 = pack2(xv.x), x1 = pack2(xv.y);
            fma2(acc[0][0], w01.x, x0); fma2(acc[0][1], w01.x, x1);
            fma2(acc[1][0], w01.y, x0); fma2(acc[1][1], w01.y, x1);
            fma2(acc[2][0], w23.x, x0); fma2(acc[2][1], w23.x, x1);
            fma2(acc[3][0], w23.y, x0); fma2(acc[3][1], w23.y, x1);
        }
        __syncthreads();
    }
#pragma unroll
    for (int p = 0; p < 4; ++p) {
        int h0 = hbase + (hg << 3) + 2 * p;
        float yA0, yA1, yB0, yB1;
        unpack2(yA0, yA1, acc[p][0]);   // rows h0, h0+1 @ b0
        unpack2(yB0, yB1, acc[p][1]);   // rows h0, h0+1 @ b1
        float bi0 = b_in[h0], bi1 = b_in[h0 + 1];
        size_t base = (size_t)t * (HH * BB) + (size_t)h0 * BB + (bg << 1);
        *reinterpret_cast<float2*>(g_xproj + base)      = make_float2(yA0 + bi0, yB0 + bi0);
        *reinterpret_cast<float2*>(g_xproj + base + BB) = make_float2(yA1 + bi1, yB1 + bi1);
    }
}

// ==========================================================================
// Kernel 2: persistent recurrent scan. grid = 2 b-halves x nrg row-groups,
// all CTAs resident (grid <= SM count). 512 threads: 16 k-slices x 32 lanes.
// acc[p] = {D[row0+2p][b], D[row0+2p+1][b]} via f32x2.
// ==========================================================================
__global__ void __launch_bounds__(512, 1) rnn_step_kernel(
    const float* __restrict__ w_rec, const float* __restrict__ b_rec,
    const float* __restrict__ w_out, const float* __restrict__ b_out,
    const float* __restrict__ scale, const float* __restrict__ shift)
{
    extern __shared__ float smem[];
    float* Ws = smem;                                           // [1024 * MAXR]
    unsigned long long* red =
        reinterpret_cast<unsigned long long*>(smem + HH * MAXR); // [16][NPAIR][32]

    const int tid = threadIdx.x;
    const int cta = blockIdx.x;
    const int ncta = gridDim.x;
    const int nrg = ncta >> 1;
    const int rg = cta >> 1;
    const int bhalf = cta & 1;
    const int base_r = 1280 / nrg;
    const int extra = 1280 - base_r * nrg;
    const int row0 = rg * base_r + (rg < extra ? rg : extra);
    const int nrows = base_r + (rg < extra ? 1 : 0);

    // zero then stage this CTA's weight rows once ([k][r], r stride MAXR)
    for (int idx = tid; idx < HH * MAXR; idx += 512) Ws[idx] = 0.f;
    __syncthreads();
    for (int r = 0; r < nrows; ++r) {
        int gr = row0 + r;
        const float* src = (gr < HH) ? (w_rec + (size_t)gr * HH)
                                     : (w_out + (size_t)(gr - HH) * HH);
        for (int k = tid; k < HH; k += 512)
            Ws[k * MAXR + r] = src[k];
    }
    __syncthreads();

    const int lane = tid & 31;
    const int ks = tid >> 5;              // 0..15, 64 k each
    const int k0 = ks << 6;
    const int bglob = (bhalf << 5) + lane;

    // ---- epilogue role: thread tid handles entry (p_ep, b_ep) if tid < 288
    const bool has_ep = (tid < NPAIR * 32);
    const int p_ep = tid >> 5;
    const int b_ep = tid & 31;
    const int bg_ep = (bhalf << 5) + b_ep;
    int gr0 = 0, gr1 = 0;
    bool v0 = false, v1 = false, rec0 = false, rec1 = false;
    float m0 = 0, a0 = 0, s0 = 0, m1 = 0, a1 = 0, s1 = 0;
    if (has_ep) {
        int r0l = 2 * p_ep, r1l = 2 * p_ep + 1;
        v0 = r0l < nrows; v1 = r1l < nrows;
        gr0 = row0 + r0l; gr1 = row0 + r1l;
        if (v0) {
            if (gr0 < HH) { rec0 = true; a0 = b_rec[gr0]; }
            else { m0 = scale[gr0 - HH]; a0 = b_out[gr0 - HH]; s0 = shift[gr0 - HH]; }
        }
        if (v1) {
            if (gr1 < HH) { rec1 = true; a1 = b_rec[gr1]; }
            else { m1 = scale[gr1 - HH]; a1 = b_out[gr1 - HH]; s1 = shift[gr1 - HH]; }
        }
    }

    for (int j = 0; j <= TT; ++j) {
        // prefetch epilogue x (rec rows) — overlaps with FMA loop
        float x0 = 0.f, x1 = 0.f;
        if (has_ep && j < TT) {
            if (v0 && rec0) x0 = g_xproj[(size_t)j * (HH * BB) + (size_t)gr0 * BB + bg_ep];
            if (v1 && rec1) x1 = g_xproj[(size_t)j * (HH * BB) + (size_t)gr1 * BB + bg_ep];
        }

        unsigned long long acc[NPAIR];
#pragma unroll
        for (int p = 0; p < NPAIR; ++p) acc[p] = 0ull;

        if (j > 0) {
            const float* hp = g_hall + (size_t)(j - 1) * (HH * BB) + (size_t)k0 * BB + bglob;
            const float* wp = Ws + k0 * MAXR;
            float hbuf[8];
#pragma unroll
            for (int u = 0; u < 8; ++u) hbuf[u] = hp[u * BB];
#pragma unroll
            for (int kk = 0; kk < 64; kk += 8) {
                float hn[8];
                if (kk + 8 < 64) {
#pragma unroll
                    for (int u = 0; u < 8; ++u) hn[u] = hp[(kk + 8 + u) * BB];
                }
#pragma unroll
                for (int u = 0; u < 8; ++u) {
                    unsigned long long hv = pack2(hbuf[u]);
                    const float* w = wp + (kk + u) * MAXR;
                    ulonglong2 wA = *reinterpret_cast<const ulonglong2*>(w);
                    ulonglong2 wB = *reinterpret_cast<const ulonglong2*>(w + 4);
                    ulonglong2 wC = *reinterpret_cast<const ulonglong2*>(w + 8);
                    ulonglong2 wD = *reinterpret_cast<const ulonglong2*>(w + 12);
                    unsigned long long wE = *reinterpret_cast<const unsigned long long*>(w + 16);
                    fma2(acc[0], wA.x, hv); fma2(acc[1], wA.y, hv);
                    fma2(acc[2], wB.x, hv); fma2(acc[3], wB.y, hv);
                    fma2(acc[4], wC.x, hv); fma2(acc[5], wC.y, hv);
                    fma2(acc[6], wD.x, hv); fma2(acc[7], wD.y, hv);
                    fma2(acc[8], wE, hv);
                }
                if (kk + 8 < 64) {
#pragma unroll
                    for (int u = 0; u < 8; ++u) hbuf[u] = hn[u];
                }
            }
        }

        // k-slice reduction through SMEM
#pragma unroll
        for (int p = 0; p < NPAIR; ++p)
            red[(ks * NPAIR + p) * 32 + lane] = acc[p];
        __syncthreads();

        if (has_ep) {
            unsigned long long s = red[p_ep * 32 + b_ep];
#pragma unroll
            for (int q = 1; q < 16; ++q)
                s = add2(s, red[(q * NPAIR + p_ep) * 32 + b_ep]);
            float y0, y1; unpack2(y0, y1, s);
            if (v0) {
                if (rec0) {
                    if (j < TT)
                        g_hall[(size_t)j * (HH * BB) + (size_t)gr0 * BB + bg_ep] =
                            fmaxf(y0 + a0 + x0, 0.0f);
                } else if (j > 0) {
                    g_outs[(size_t)(j - 1) * (OO * BB) + (size_t)(gr0 - HH) * BB + bg_ep] =
                        m0 * (y0 + a0) - s0;
                }
            }
            if (v1) {
                if (rec1) {
                    if (j < TT)
                        g_hall[(size_t)j * (HH * BB) + (size_t)gr1 * BB + bg_ep] =
                            fmaxf(y1 + a1 + x1, 0.0f);
                } else if (j > 0) {
                    g_outs[(size_t)(j - 1) * (OO * BB) + (size_t)(gr1 - HH) * BB + bg_ep] =
                        m1 * (y1 + a1) - s1;
                }
            }
        }

        // ---- grid barrier ----
        __syncthreads();
        if (tid == 0) {
            unsigned my = g_gen;
            __threadfence();
            if (atomicAdd(&g_cnt, 1u) == (unsigned)(ncta - 1)) {
                g_cnt = 0;
                __threadfence();
                g_gen = my + 1;
            } else {
                while (g_gen == my) { }
                __threadfence();
            }
        }
        __syncthreads();
    }
}

// ==========================================================================
// Kernel 3: batched plane transpose  src[t][r][c] -> dst[c][t*R + r]
// ==========================================================================
__global__ void transpose_kernel(float* __restrict__ dst, int R, int which)
{
    __shared__ float tile[32][33];
    const float* src = which ? g_hall : g_outs;
    const int t = blockIdx.z;
    const int r0 = blockIdx.x << 5, c0 = blockIdx.y << 5;
    const int x = threadIdx.x, y = threadIdx.y;
    const float* s = src + (size_t)t * R * BB;
#pragma unroll
    for (int jj = 0; jj < 32; jj += 8)
        tile[y + jj][x] = s[(size_t)(r0 + y + jj) * BB + c0 + x];
    __syncthreads();
    const size_t TR = (size_t)TT * R;
#pragma unroll
    for (int jj = 0; jj < 32; jj += 8)
        dst[(size_t)(c0 + y + jj) * TR + (size_t)t * R + r0 + x] = tile[x][y + jj];
}

// ==========================================================================
extern "C" void kernel_launch(void* const* d_in, const int* in_sizes, int n_in,
                              void* d_out, int out_size)
{
    (void)in_sizes; (void)n_in; (void)out_size;
    const float* inputs = (const float*)d_in[0];
    const float* w_rec  = (const float*)d_in[1];
    const float* b_rec  = (const float*)d_in[2];
    const float* w_in   = (const float*)d_in[3];
    const float* b_in   = (const float*)d_in[4];
    const float* w_out  = (const float*)d_in[5];
    const float* b_out  = (const float*)d_in[6];
    const float* scale  = (const float*)d_in[7];
    const float* shift  = (const float*)d_in[8];
    float* out = (float*)d_out;

    xproj_kernel<<<dim3(HH / 64, TT), 256>>>(inputs, w_in, b_in);

    int dev = 0, sms = 148;
    cudaGetDevice(&dev);
    cudaDeviceGetAttribute(&sms, cudaDevAttrMultiProcessorCount, dev);
    int ncta = sms & ~1;
    if (ncta > 152) ncta = 152;

    const int smem_bytes = HH * MAXR * 4 + 16 * NPAIR * 32 * 8;   // 81920 + 36864
    cudaFuncSetAttribute(rnn_step_kernel,
                         cudaFuncAttributeMaxDynamicSharedMemorySize, smem_bytes);
    rnn_step_kernel<<<ncta, 512, smem_bytes>>>(w_rec, b_rec, w_out, b_out, scale, shift);

    transpose_kernel<<<dim3(OO / 32, BB / 32, TT), dim3(32, 8)>>>(out, OO, 0);
    transpose_kernel<<<dim3(HH / 32, BB / 32, TT), dim3(32, 8)>>>(
        out + (size_t)BB * TT * OO, HH, 1);
}